// round 14
// baseline (speedup 1.0000x reference)
#include <cuda_runtime.h>
#include <cuda_fp16.h>

// LightGCN 3-layer propagation. CSR (dst-sorted), atomic-free reduction.
// fp16 intermediates, 8-lane uint4 props. R13 structure; the prop inner loop
// now accumulates with packed fma.rn.f32x2 (FFMA2) — half the FMA issue slots.

#define NUM_USERS 100000
#define NUM_ITEMS 50000
#define NN        150000
#define DIM       64
#define EDGES     1250000

#define NQ  (NN * 16)          // float4 count of one fp32 embedding buffer
#define UQ  (NUM_USERS * 16)

#define SCAN_B 256
#define NBLK   ((NN + SCAN_B - 1) / SCAN_B)   // 586
#define OFFSZ  (NBLK * SCAN_B)

// Device-global scratch. fp16 bufs 3x19.2MB, edges 10MB, rank 5MB.
__device__ uint4 g_embh[NN * 8];    // uw||iw fp16 (row = 8 uint4 = 64 halves)
__device__ uint4 g_c1h [NN * 8];    // layer-1 result, fp16
__device__ uint4 g_c2h [NN * 8];    // layer-2 result, fp16
__device__ int   g_cnt [NN];        // in-degree (zeroed by scan after read)
__device__ float g_rs  [NN];        // rs[x] = deg>0 ? rsqrt(deg) : 0
__device__ int   g_rank[EDGES];     // per-edge arrival rank within its dst
__device__ int   g_off [OFFSZ + 1]; // block-LOCAL exclusive prefix of cnt
__device__ int   g_bsum[NBLK];      // exclusive block sums
__device__ int2  g_edge[EDGES];     // {src, __float_as_int(rs[src])} sorted by dst
__device__ int   g_done;            // last-block-done counter (self-resetting)

// ---------------------------------------------------------------------------
// packed f32x2 helpers (FFMA2 path — sm_100+ only via PTX)
// ---------------------------------------------------------------------------
__device__ __forceinline__ unsigned long long pack_f32x2(float lo, float hi) {
    unsigned long long r;
    asm("mov.b64 %0, {%1, %2};" : "=l"(r) : "f"(lo), "f"(hi));
    return r;
}
__device__ __forceinline__ void unpack_f32x2(unsigned long long v, float& lo, float& hi) {
    asm("mov.b64 {%0, %1}, %2;" : "=f"(lo), "=f"(hi) : "l"(v));
}
__device__ __forceinline__ void fma_f32x2(unsigned long long& acc,
                                          unsigned long long a,
                                          unsigned long long b) {
    asm("fma.rn.f32x2 %0, %1, %2, %0;" : "+l"(acc) : "l"(a), "l"(b));
}
__device__ __forceinline__ void mul_f32x2(unsigned long long& acc,
                                          unsigned long long b) {
    asm("mul.rn.f32x2 %0, %0, %1;" : "+l"(acc) : "l"(b));
}

// Accumulate one fp16 row fragment (uint4 = 8 halves) into 4 packed accums.
__device__ __forceinline__ void accp(unsigned long long& a01, unsigned long long& a23,
                                     unsigned long long& b01, unsigned long long& b23,
                                     uint4 v, unsigned long long ww) {
    float2 q0 = __half22float2(*reinterpret_cast<const __half2*>(&v.x));
    float2 q1 = __half22float2(*reinterpret_cast<const __half2*>(&v.y));
    float2 q2 = __half22float2(*reinterpret_cast<const __half2*>(&v.z));
    float2 q3 = __half22float2(*reinterpret_cast<const __half2*>(&v.w));
    fma_f32x2(a01, pack_f32x2(q0.x, q0.y), ww);
    fma_f32x2(a23, pack_f32x2(q1.x, q1.y), ww);
    fma_f32x2(b01, pack_f32x2(q2.x, q2.y), ww);
    fma_f32x2(b23, pack_f32x2(q3.x, q3.y), ww);
}

// plain-float accumulate (used outside the hot loop)
__device__ __forceinline__ void acc_h8(float4& ra, float4& rb, uint4 v, float w) {
    float2 q0 = __half22float2(*reinterpret_cast<const __half2*>(&v.x));
    float2 q1 = __half22float2(*reinterpret_cast<const __half2*>(&v.y));
    float2 q2 = __half22float2(*reinterpret_cast<const __half2*>(&v.z));
    float2 q3 = __half22float2(*reinterpret_cast<const __half2*>(&v.w));
    ra.x += q0.x * w; ra.y += q0.y * w; ra.z += q1.x * w; ra.w += q1.y * w;
    rb.x += q2.x * w; rb.y += q2.y * w; rb.z += q3.x * w; rb.w += q3.y * w;
}

// ---------------------------------------------------------------------------
// Per-warp dtype detection: all warps sample the SAME first 8 int64 slots.
// ---------------------------------------------------------------------------
__device__ __forceinline__ bool detect_is32(const void* edge) {
    int lid = threadIdx.x & 31;
    bool bad = false;
    if (lid < 8) {
        long long v = ((const long long*)edge)[lid];
        bad = (v < 0 || v >= (long long)NN);
    }
    return __ballot_sync(0xffffffffu, bad) != 0;
}

// ---------------------------------------------------------------------------
// histogram + per-edge rank; grid-stride fp16 concat uw||iw -> g_embh rides
// in the atomic latency shadow.
// ---------------------------------------------------------------------------
__global__ void histrank_kernel(const void* edge,
                                const float* __restrict__ uw,
                                const float* __restrict__ iw) {
    int t = blockIdx.x * blockDim.x + threadIdx.x;
    int stride = gridDim.x * blockDim.x;
    bool is32 = detect_is32(edge);

    uint2* eh = (uint2*)g_embh;
    for (int i = t; i < NQ; i += stride) {
        float4 v = (i < UQ) ? ((const float4*)uw)[i]
                            : ((const float4*)iw)[i - UQ];
        __half2 p0 = __floats2half2_rn(v.x, v.y);
        __half2 p1 = __floats2half2_rn(v.z, v.w);
        eh[i] = make_uint2(*reinterpret_cast<unsigned*>(&p0),
                           *reinterpret_cast<unsigned*>(&p1));
    }

    if (t >= EDGES) return;
    int d;
    if (is32) d = ((const int*)edge)[EDGES + t];
    else      d = (int)((const long long*)edge)[EDGES + t];
    g_rank[t] = atomicAdd(&g_cnt[d], 1);
}

// ---------------------------------------------------------------------------
// Fused scan: per-block exclusive scan of cnt (+ rs emit + cnt reset), then
// the LAST block to finish scans the 586 block sums (no extra launch).
// ---------------------------------------------------------------------------
__device__ __forceinline__ int warp_incl_scan(int v, int lid) {
    #pragma unroll
    for (int o = 1; o < 32; o <<= 1) {
        int t = __shfl_up_sync(0xffffffffu, v, o);
        if (lid >= o) v += t;
    }
    return v;
}

__global__ void __launch_bounds__(SCAN_B)
scan_kernel() {
    __shared__ int wsum[8];
    __shared__ int s_last;
    int b = blockIdx.x;
    int i = b * SCAN_B + threadIdx.x;
    int v = (i < NN) ? g_cnt[i] : 0;
    if (i < NN) {
        g_rs[i]  = (v > 0) ? rsqrtf((float)v) : 0.f;
        g_cnt[i] = 0;                                  // reset for next replay
    }
    int wid = threadIdx.x >> 5, lid = threadIdx.x & 31;
    int incl = warp_incl_scan(v, lid);
    if (lid == 31) wsum[wid] = incl;
    __syncthreads();
    if (wid == 0) {
        int s = (lid < 8) ? wsum[lid] : 0;
        #pragma unroll
        for (int o = 1; o < 8; o <<= 1) {
            int t = __shfl_up_sync(0xffffffffu, s, o);
            if (lid >= o) s += t;
        }
        if (lid < 8) wsum[lid] = s;
    }
    __syncthreads();
    int base = (wid > 0) ? wsum[wid - 1] : 0;
    g_off[i] = base + incl - v;                        // block-local exclusive
    if (threadIdx.x == SCAN_B - 1) g_bsum[b] = base + incl;
    if (i == 0) g_off[OFFSZ] = 0;

    __threadfence();
    if (threadIdx.x == 0) {
        int done = atomicAdd(&g_done, 1);
        s_last = (done == (int)gridDim.x - 1) ? 1 : 0;
    }
    __syncthreads();
    if (!s_last) return;

    __shared__ int wsum2[8];
    int b3 = threadIdx.x * 3;
    int a0 = (b3     < NBLK) ? g_bsum[b3]     : 0;
    int a1 = (b3 + 1 < NBLK) ? g_bsum[b3 + 1] : 0;
    int a2 = (b3 + 2 < NBLK) ? g_bsum[b3 + 2] : 0;
    int tsum = a0 + a1 + a2;
    int incl2 = warp_incl_scan(tsum, lid);
    if (lid == 31) wsum2[wid] = incl2;
    __syncthreads();
    if (wid == 0) {
        int s = (lid < 8) ? wsum2[lid] : 0;
        #pragma unroll
        for (int o = 1; o < 8; o <<= 1) {
            int t = __shfl_up_sync(0xffffffffu, s, o);
            if (lid >= o) s += t;
        }
        if (lid < 8) wsum2[lid] = s;
    }
    __syncthreads();
    int tbase = ((wid > 0) ? wsum2[wid - 1] : 0) + incl2 - tsum;
    if (b3     < NBLK) g_bsum[b3]     = tbase;
    if (b3 + 1 < NBLK) g_bsum[b3 + 1] = tbase + a0;
    if (b3 + 2 < NBLK) g_bsum[b3 + 2] = tbase + a0 + a1;
    if (threadIdx.x == 0) g_done = 0;                  // reset for next replay
}

// ---------------------------------------------------------------------------
// CSR fill: pos = local_off[d] + bsum[d>>8] + rank[e]; stores {src, rs[src]}.
// ---------------------------------------------------------------------------
__global__ void fill_kernel(const void* edge) {
    int e = blockIdx.x * blockDim.x + threadIdx.x;
    if (e >= EDGES) return;
    bool is32 = detect_is32(edge);
    int s, d;
    if (is32) {
        const int* ei = (const int*)edge;
        s = ei[e];
        d = ei[EDGES + e];
    } else {
        const long long* ei = (const long long*)edge;
        s = (int)ei[e];
        d = (int)ei[EDGES + e];
    }
    float w = g_rs[s];
    int pos = g_off[d] + g_bsum[d >> 8] + g_rank[e];
    g_edge[pos] = make_int2(s, __float_as_int(w));
}

// ---------------------------------------------------------------------------
// Propagate. 8 lanes per node; lane c owns halves [8c..8c+7] (16B uint4).
// fp16 gathers, packed f32x2 FMA accumulate, scale by rs[n] (mul.f32x2).
// ---------------------------------------------------------------------------
template<int MODE>
__global__ void __launch_bounds__(256)
prop_kernel(const uint4* __restrict__ cur,
            const float* __restrict__ uw,
            const float* __restrict__ iw,
            const uint4* __restrict__ c1,
            uint4* __restrict__ nxt,
            float* __restrict__ out) {
    int t = blockIdx.x * blockDim.x + threadIdx.x;
    int n = t >> 3;
    int c = t & 7;
    if (n >= NN) return;
    int j   = g_off[n]     + g_bsum[n >> 8];
    int end = g_off[n + 1] + g_bsum[(n + 1) >> 8];

    unsigned long long a01 = 0, a23 = 0, b01 = 0, b23 = 0;

    const int2* __restrict__ ge = g_edge;
    for (; j + 4 <= end; j += 4) {
        int2 e0 = ge[j];
        int2 e1 = ge[j + 1];
        int2 e2 = ge[j + 2];
        int2 e3 = ge[j + 3];
        uint4 v0 = cur[e0.x * 8 + c];
        uint4 v1 = cur[e1.x * 8 + c];
        uint4 v2 = cur[e2.x * 8 + c];
        uint4 v3 = cur[e3.x * 8 + c];
        float w0 = __int_as_float(e0.y), w1 = __int_as_float(e1.y);
        float w2 = __int_as_float(e2.y), w3 = __int_as_float(e3.y);
        accp(a01, a23, b01, b23, v0, pack_f32x2(w0, w0));
        accp(a01, a23, b01, b23, v1, pack_f32x2(w1, w1));
        accp(a01, a23, b01, b23, v2, pack_f32x2(w2, w2));
        accp(a01, a23, b01, b23, v3, pack_f32x2(w3, w3));
    }
    #pragma unroll 1
    for (; j < end; ++j) {
        int2 e0 = ge[j];
        uint4 v0 = cur[e0.x * 8 + c];
        float w0 = __int_as_float(e0.y);
        accp(a01, a23, b01, b23, v0, pack_f32x2(w0, w0));
    }

    float wn = g_rs[n];                    // rs[dst]
    unsigned long long wnw = pack_f32x2(wn, wn);
    mul_f32x2(a01, wnw);
    mul_f32x2(a23, wnw);
    mul_f32x2(b01, wnw);
    mul_f32x2(b23, wnw);

    float4 ra, rb;
    unpack_f32x2(a01, ra.x, ra.y);
    unpack_f32x2(a23, ra.z, ra.w);
    unpack_f32x2(b01, rb.x, rb.y);
    unpack_f32x2(b23, rb.z, rb.w);

    if (MODE == 1) {
        int fo = n * 16 + c * 2;
        const float4* ew = (n < NUM_USERS) ? (const float4*)uw
                                           : (const float4*)iw - UQ;
        float4 ea = ew[fo];
        float4 eb = ew[fo + 1];
        uint4 uc1 = c1[n * 8 + c];         // layer-1 (fp16)
        uint4 uc2 = cur[n * 8 + c];        // layer-2 (fp16)
        float4 za = make_float4(0.f, 0.f, 0.f, 0.f);
        float4 zb = make_float4(0.f, 0.f, 0.f, 0.f);
        acc_h8(za, zb, uc1, 1.0f);
        acc_h8(za, zb, uc2, 1.0f);
        float4 oa, ob;
        oa.x = (ea.x + za.x + ra.x) * 0.25f;
        oa.y = (ea.y + za.y + ra.y) * 0.25f;
        oa.z = (ea.z + za.z + ra.z) * 0.25f;
        oa.w = (ea.w + za.w + ra.w) * 0.25f;
        ob.x = (eb.x + zb.x + rb.x) * 0.25f;
        ob.y = (eb.y + zb.y + rb.y) * 0.25f;
        ob.z = (eb.z + zb.z + rb.z) * 0.25f;
        ob.w = (eb.w + zb.w + rb.w) * 0.25f;
        float4* op = (float4*)out;
        op[fo]          = oa;
        op[fo + 1]      = ob;
        op[NQ + fo]     = oa;
        op[NQ + fo + 1] = ob;
    } else {
        __half2 p0 = __floats2half2_rn(ra.x, ra.y);
        __half2 p1 = __floats2half2_rn(ra.z, ra.w);
        __half2 p2 = __floats2half2_rn(rb.x, rb.y);
        __half2 p3 = __floats2half2_rn(rb.z, rb.w);
        nxt[n * 8 + c] = make_uint4(*reinterpret_cast<unsigned*>(&p0),
                                    *reinterpret_cast<unsigned*>(&p1),
                                    *reinterpret_cast<unsigned*>(&p2),
                                    *reinterpret_cast<unsigned*>(&p3));
    }
}

// ---------------------------------------------------------------------------
extern "C" void kernel_launch(void* const* d_in, const int* in_sizes, int n_in,
                              void* d_out, int out_size) {
    const void*  edge = d_in[0];
    const float* uw   = (const float*)d_in[1];
    const float* iw   = (const float*)d_in[2];
    float*       out  = (float*)d_out;

    uint4* E  = nullptr;
    uint4* C1 = nullptr;
    uint4* C2 = nullptr;
    cudaGetSymbolAddress((void**)&E,  g_embh);
    cudaGetSymbolAddress((void**)&C1, g_c1h);
    cudaGetSymbolAddress((void**)&C2, g_c2h);

    const int T = 256;
    const int grid_e = (EDGES + T - 1) / T;
    const int grid_p = (NN * 8 + T - 1) / T;   // 8 lanes/node

    histrank_kernel<<<grid_e, T>>>(edge, uw, iw);  // + fp16 concat
    scan_kernel<<<NBLK, SCAN_B>>>();               // scan1+scan2 fused
    fill_kernel<<<grid_e, T>>>(edge);

    // layer 1: emb_h -> c1_h
    prop_kernel<0><<<grid_p, T>>>(E,  uw, iw, nullptr, C1, nullptr);
    // layer 2: c1_h -> c2_h
    prop_kernel<0><<<grid_p, T>>>(C1, uw, iw, nullptr, C2, nullptr);
    // layer 3: gather c2_h; finalize with emb(fp32) + c1_h + c2_h, duplicated
    prop_kernel<1><<<grid_p, T>>>(C2, uw, iw, C1, nullptr, out);
}